// round 6
// baseline (speedup 1.0000x reference)
#include <cuda_runtime.h>
#include <cstdint>

#define T_NODES 80000          // B*N = 16*5000
#define C_DIM   128
#define HF_DIM  128            // H*F = 2*64
#define E_EDGES 1280000
#define NEG_SLOPE 0.2f
#define SCAN_BLOCKS ((T_NODES + 255) / 256)   // 313

// ---------------- static device scratch (zero-initialized at load) ----------------
__device__ __align__(16) float g_xl[T_NODES * HF_DIM];   // 40.96 MB
__device__ __align__(16) float g_xr[T_NODES * HF_DIM];   // 40.96 MB
__device__ int g_deg[T_NODES];            // invariant: zero at kernel_launch entry
__device__ int g_off[T_NODES + 1];
__device__ int g_cur[T_NODES];
__device__ int g_csr_src[E_EDGES + 8];    // +8 pad (never written, stays 0)
// packed lookback word: low 2 bits = state, high 32 = value; zero at entry
__device__ volatile unsigned long long g_scan_word[SCAN_BLOCKS];

// ---------------- tf32 helpers ----------------
__device__ __forceinline__ uint32_t f2tf32(float v) {
    uint32_t r;
    asm("cvt.rna.tf32.f32 %0, %1;" : "=r"(r) : "f"(v));
    return r;
}
__device__ __forceinline__ void mma_tf32(float* d, const uint32_t* a, const uint32_t* b) {
    asm("mma.sync.aligned.m16n8k8.row.col.f32.tf32.tf32.f32 "
        "{%0,%1,%2,%3}, {%4,%5,%6,%7}, {%8,%9}, {%0,%1,%2,%3};"
        : "+f"(d[0]), "+f"(d[1]), "+f"(d[2]), "+f"(d[3])
        : "r"(a[0]), "r"(a[1]), "r"(a[2]), "r"(a[3]),
          "r"(b[0]), "r"(b[1]));
}

// ---------------- K1: tf32 tensor-core GEMMs (A hi/lo, 2-pass) + hidden hist ----
// CTA: 128x128 output tile, 8 warps (4m x 2n), warp tile 32x64.
// K chunked by 16 (2 k8 steps per chunk). smem holds fragment-ordered tf32.
__global__ void __launch_bounds__(256, 2)
gemm_kernel(const float* __restrict__ X,
            const float* __restrict__ Wl, const float* __restrict__ bl,
            const float* __restrict__ Wr, const float* __restrict__ br,
            const int* __restrict__ ei, int E) {
    // A_s: [k8(2)][m_atom(8)][hl(2)][lane(32)][reg(4)] = 4096 u32 (16KB)
    // B_s: [k8(2)][n_atom(16)][lane(32)][reg(2)]       = 2048 u32 (8KB)
    __shared__ uint32_t A_s[4096];
    __shared__ uint32_t B_s[2048];

    const int which = blockIdx.y;
    const float* __restrict__ W    = which ? Wr : Wl;
    const float* __restrict__ bvec = which ? br : bl;
    float* __restrict__ Y = which ? g_xr : g_xl;

    const int t = threadIdx.x;

    // histogram (fire-and-forget REDs, hidden under tensor work)
    {
        const int nthr = gridDim.x * gridDim.y * 256;
        int gid = (blockIdx.y * gridDim.x + blockIdx.x) * 256 + t;
        const int* __restrict__ dsts = ei + E;
        if ((E & 3) == 0) {
            const int4* __restrict__ d4 = (const int4*)dsts;
            for (int e = gid; e < (E >> 2); e += nthr) {
                int4 v = d4[e];
                atomicAdd(&g_deg[v.x], 1);
                atomicAdd(&g_deg[v.y], 1);
                atomicAdd(&g_deg[v.z], 1);
                atomicAdd(&g_deg[v.w], 1);
            }
        } else {
            for (int e = gid; e < E; e += nthr)
                atomicAdd(&g_deg[dsts[e]], 1);
        }
    }

    const int lane = t & 31;
    const int wid  = t >> 5;
    const int wm   = wid & 3;     // warp row group (32 rows)
    const int wn   = wid >> 2;    // warp col group (64 cols)
    const int rowBase = blockIdx.x * 128;

    float d[2][8][4];
#pragma unroll
    for (int ma = 0; ma < 2; ma++)
#pragma unroll
        for (int na = 0; na < 8; na++)
#pragma unroll
            for (int r = 0; r < 4; r++) d[ma][na][r] = 0.f;

#pragma unroll 1
    for (int kc = 0; kc < 128; kc += 16) {
        // ---- stage A chunk (128 rows x 16 k), split hi/lo ----
#pragma unroll
        for (int q = 0; q < 2; q++) {
            int idx = t * 2 + q;               // 0..511
            int row = idx >> 2;
            int kq  = (idx & 3) * 4;
            float4 v = *(const float4*)&X[(size_t)(rowBase + row) * C_DIM + kc + kq];
            float vv[4] = { v.x, v.y, v.z, v.w };
            int ma = row >> 4;
            int r  = row & 15;
#pragma unroll
            for (int j = 0; j < 4; j++) {
                int kk  = kq + j;
                int k8  = kk >> 3;
                int kin = kk & 7;
                int ln  = (r & 7) * 4 + (kin & 3);
                int rg  = (r >> 3) | ((kin >> 2) << 1);
                uint32_t hi = f2tf32(vv[j]);
                uint32_t lo = f2tf32(vv[j] - __uint_as_float(hi));
                int base = (((k8 * 8 + ma) * 2) * 32 + ln) * 4 + rg;
                A_s[base]       = hi;
                A_s[base + 128] = lo;          // hl stride = 32*4
            }
        }
        // ---- stage B chunk (16 k x 128 n), single tf32 ----
#pragma unroll
        for (int q = 0; q < 2; q++) {
            int idx = t * 2 + q;               // 0..511
            int kk  = idx >> 5;
            int n4  = (idx & 31) * 4;
            float4 v = *(const float4*)&W[(size_t)(kc + kk) * HF_DIM + n4];
            float vv[4] = { v.x, v.y, v.z, v.w };
            int k8  = kk >> 3;
            int kin = kk & 7;
#pragma unroll
            for (int j = 0; j < 4; j++) {
                int n   = n4 + j;
                int na  = n >> 3;
                int nin = n & 7;
                int ln  = nin * 4 + (kin & 3);
                int rg  = kin >> 2;
                B_s[((k8 * 16 + na) * 32 + ln) * 2 + rg] = f2tf32(vv[j]);
            }
        }
        __syncthreads();

#pragma unroll
        for (int k8 = 0; k8 < 2; k8++) {
            uint32_t ah[2][4], al[2][4], bf[8][2];
#pragma unroll
            for (int ma = 0; ma < 2; ma++) {
                int base = ((k8 * 8 + wm * 2 + ma) * 2 * 32 + lane) * 4;
                uint4 h = *(const uint4*)&A_s[base];
                uint4 l = *(const uint4*)&A_s[base + 128];
                ah[ma][0] = h.x; ah[ma][1] = h.y; ah[ma][2] = h.z; ah[ma][3] = h.w;
                al[ma][0] = l.x; al[ma][1] = l.y; al[ma][2] = l.z; al[ma][3] = l.w;
            }
#pragma unroll
            for (int na = 0; na < 8; na++) {
                uint2 b2 = *(const uint2*)&B_s[((k8 * 16 + wn * 8 + na) * 32 + lane) * 2];
                bf[na][0] = b2.x; bf[na][1] = b2.y;
            }
#pragma unroll
            for (int ma = 0; ma < 2; ma++)
#pragma unroll
                for (int na = 0; na < 8; na++) {
                    mma_tf32(d[ma][na], ah[ma], bf[na]);
                    mma_tf32(d[ma][na], al[ma], bf[na]);
                }
        }
        __syncthreads();
    }

    // ---- epilogue: add bias, store ----
    const int quad = lane >> 2;
    const int tq   = lane & 3;
#pragma unroll
    for (int ma = 0; ma < 2; ma++) {
        int row0 = rowBase + wm * 32 + ma * 16 + quad;
        int row1 = row0 + 8;
#pragma unroll
        for (int na = 0; na < 8; na++) {
            int col = wn * 64 + na * 8 + tq * 2;
            float2 bb = *(const float2*)&bvec[col];
            float2 o0 = { d[ma][na][0] + bb.x, d[ma][na][1] + bb.y };
            float2 o1 = { d[ma][na][2] + bb.x, d[ma][na][3] + bb.y };
            *(float2*)&Y[(size_t)row0 * HF_DIM + col] = o0;
            *(float2*)&Y[(size_t)row1 * HF_DIM + col] = o1;
        }
    }
}

// ---------------- K2: single-pass scan (warp-parallel lookback) ---------------
__global__ void __launch_bounds__(256)
scan_kernel() {
    const int b = blockIdx.x, t = threadIdx.x;
    const int lane = t & 31, w = t >> 5;
    int i = b * 256 + t;
    int v = (i < T_NODES) ? g_deg[i] : 0;
    if (i < T_NODES) g_deg[i] = 0;          // self-clean for next launch

    int x = v;
#pragma unroll
    for (int d = 1; d < 32; d <<= 1) {
        int y = __shfl_up_sync(0xffffffffu, x, d);
        if (lane >= d) x += y;
    }
    __shared__ int wt[8];
    if (lane == 31) wt[w] = x;
    __syncthreads();
    if (t < 8) {
        int y = wt[t];
#pragma unroll
        for (int d = 1; d < 8; d <<= 1) {
            int z = __shfl_up_sync(0x000000ffu, y, d);
            if (t >= d) y += z;
        }
        wt[t] = y;
    }
    __syncthreads();
    int incl  = x + (w ? wt[w - 1] : 0);
    int total = wt[7];

    __shared__ int s_excl;
    if (w == 0) {
        if (lane == 0)
            g_scan_word[b] = ((unsigned long long)(unsigned)total << 32) | 1ull;

        int excl = 0;
        int base = b - 1;
        while (base >= 0) {
            int idx = base - lane;
            unsigned long long wv = 0; int st = 0;
            if (idx >= 0) {
                do { wv = g_scan_word[idx]; st = (int)(wv & 3ull); } while (st == 0);
            }
            int val = (int)(wv >> 32);
            unsigned pm = __ballot_sync(0xffffffffu, idx >= 0 && st == 2);
            if (pm) {
                int fl = __ffs(pm) - 1;
                int contrib = (lane <= fl) ? val : 0;
#pragma unroll
                for (int d = 16; d > 0; d >>= 1)
                    contrib += __shfl_xor_sync(0xffffffffu, contrib, d);
                excl += contrib;
                break;
            } else {
                int contrib = (idx >= 0) ? val : 0;
#pragma unroll
                for (int d = 16; d > 0; d >>= 1)
                    contrib += __shfl_xor_sync(0xffffffffu, contrib, d);
                excl += contrib;
                base -= 32;
            }
        }
        if (lane == 0) {
            g_scan_word[b] = ((unsigned long long)(unsigned)(excl + total) << 32) | 2ull;
            s_excl = excl;
        }
    }
    __syncthreads();

    int off = s_excl + incl - v;
    if (i < T_NODES) {
        g_off[i] = off;
        g_cur[i] = off;
        if (i == T_NODES - 1) g_off[T_NODES] = off + v;
    }
}

// ---------------- K3: scatter (also re-zeroes scan words) ----------------
__global__ void __launch_bounds__(256)
scatter_kernel(const int* __restrict__ ei, int E) {
    int tid = blockIdx.x * 256 + threadIdx.x;
    if (tid < SCAN_BLOCKS) g_scan_word[tid] = 0ull;   // self-clean for next launch

    int base = tid * 4;
    if ((E & 3) == 0) {
        if (base < E) {
            int4 s = *(const int4*)(ei + base);
            int4 d = *(const int4*)(ei + E + base);
            int p0 = atomicAdd(&g_cur[d.x], 1);
            int p1 = atomicAdd(&g_cur[d.y], 1);
            int p2 = atomicAdd(&g_cur[d.z], 1);
            int p3 = atomicAdd(&g_cur[d.w], 1);
            g_csr_src[p0] = s.x;
            g_csr_src[p1] = s.y;
            g_csr_src[p2] = s.z;
            g_csr_src[p3] = s.w;
        }
    } else {
        for (int e = base; e < min(base + 4, E); e++) {
            int pos = atomicAdd(&g_cur[ei[E + e]], 1);
            g_csr_src[pos] = ei[e];
        }
    }
}

// ---------------- K4: softmax + aggregation (baseline-exp, unroll-2, no clamps) -
__device__ __forceinline__ float edge_logit(float4 xs, float4 xr, float4 av) {
    float t0 = xs.x + xr.x, t1 = xs.y + xr.y, t2 = xs.z + xr.z, t3 = xs.w + xr.w;
    float l0 = fmaxf(t0, 0.f) + NEG_SLOPE * fminf(t0, 0.f);
    float l1 = fmaxf(t1, 0.f) + NEG_SLOPE * fminf(t1, 0.f);
    float l2 = fmaxf(t2, 0.f) + NEG_SLOPE * fminf(t2, 0.f);
    float l3 = fmaxf(t3, 0.f) + NEG_SLOPE * fminf(t3, 0.f);
    float p = l0 * av.x;
    p = fmaf(l1, av.y, p);
    p = fmaf(l2, av.z, p);
    p = fmaf(l3, av.w, p);
    p += __shfl_xor_sync(0xffffffffu, p, 1);
    p += __shfl_xor_sync(0xffffffffu, p, 2);
    p += __shfl_xor_sync(0xffffffffu, p, 4);
    p += __shfl_xor_sync(0xffffffffu, p, 8);
    return p;
}

__global__ void __launch_bounds__(256, 4)
agg_kernel(const float* __restrict__ att, const float* __restrict__ bias,
           float* __restrict__ out) {
    int warp_id = (blockIdx.x * blockDim.x + threadIdx.x) >> 5;
    int lane = threadIdx.x & 31;
    if (warp_id >= T_NODES) return;
    const int d = warp_id;
    const int fbase = lane * 4;

    const float4* __restrict__ xlp = (const float4*)g_xl;
    const float4* __restrict__ xrp = (const float4*)g_xr;

    float4 av  = *(const float4*)&att[fbase];
    float4 xr  = xrp[(size_t)d * 32 + lane];
    float4 xld = xlp[(size_t)d * 32 + lane];

    const float lself = edge_logit(xld, xr, av);
    float den = 1.0f;
    float4 acc = xld;

    const int beg = g_off[d];
    const int n = g_off[d + 1] - beg;

    if (n > 0) {
        const int* __restrict__ sp = g_csr_src + beg;
        // unguarded prefetch: csr padded; over-reads hit valid/zero indices
        int s2 = __ldg(&sp[2]);
        int s3 = __ldg(&sp[3]);
        float4 x0 = xlp[(size_t)__ldg(&sp[0]) * 32 + lane];
        float4 x1 = xlp[(size_t)__ldg(&sp[1]) * 32 + lane];

        for (int i = 0; i < n; i += 2) {
            float4 x2 = xlp[(size_t)s2 * 32 + lane];
            float4 x3 = xlp[(size_t)s3 * 32 + lane];
            int s4 = __ldg(&sp[i + 4]);
            int s5 = __ldg(&sp[i + 5]);

            float l0 = edge_logit(x0, xr, av);
            float l1 = edge_logit(x1, xr, av);
            float w0 = __expf(l0 - lself);
            float w1 = (i + 1 < n) ? __expf(l1 - lself) : 0.f;

            den += w0 + w1;
            acc.x = fmaf(w0, x0.x, fmaf(w1, x1.x, acc.x));
            acc.y = fmaf(w0, x0.y, fmaf(w1, x1.y, acc.y));
            acc.z = fmaf(w0, x0.z, fmaf(w1, x1.z, acc.z));
            acc.w = fmaf(w0, x0.w, fmaf(w1, x1.w, acc.w));

            x0 = x2; x1 = x3;
            s2 = s4; s3 = s5;
        }
    }

    float inv = 1.0f / den;
    float4 bv = *(const float4*)&bias[fbase];
    float4 r;
    r.x = fmaf(acc.x, inv, bv.x);
    r.y = fmaf(acc.y, inv, bv.y);
    r.z = fmaf(acc.z, inv, bv.z);
    r.w = fmaf(acc.w, inv, bv.w);
    ((float4*)out)[(size_t)d * 32 + lane] = r;
}

// ---------------- launch ----------------
extern "C" void kernel_launch(void* const* d_in, const int* in_sizes, int n_in,
                              void* d_out, int out_size) {
    const float* x    = (const float*)d_in[0];
    const int*   ei   = (const int*)d_in[1];
    const float* Wl   = (const float*)d_in[2];
    const float* bl   = (const float*)d_in[3];
    const float* Wr   = (const float*)d_in[4];
    const float* br   = (const float*)d_in[5];
    const float* att  = (const float*)d_in[6];
    const float* bias = (const float*)d_in[7];
    float* out = (float*)d_out;

    const int E = in_sizes[1] / 2;

    dim3 ggrid(T_NODES / 128, 2);
    gemm_kernel<<<ggrid, 256>>>(x, Wl, bl, Wr, br, ei, E);  // hist hidden inside

    scan_kernel<<<SCAN_BLOCKS, 256>>>();                    // zeroes g_deg
    scatter_kernel<<<(E / 4 + 255) / 256, 256>>>(ei, E);    // zeroes scan words
    agg_kernel<<<(T_NODES * 32 + 255) / 256, 256>>>(att, bias, out);
}

// round 7
// speedup vs baseline: 1.2766x; 1.2766x over previous
#include <cuda_runtime.h>
#include <cstdint>

#define T_NODES 80000          // B*N = 16*5000
#define C_DIM   128
#define HF_DIM  128            // H*F = 2*64
#define E_EDGES 1280000
#define NEG_SLOPE 0.2f
#define SCAN_BLOCKS ((T_NODES + 255) / 256)   // 313

// ---------------- static device scratch (zero-initialized at load) ----------------
__device__ __align__(16) float g_xl[T_NODES * HF_DIM];   // 40.96 MB
__device__ __align__(16) float g_xr[T_NODES * HF_DIM];   // 40.96 MB
__device__ int g_deg[T_NODES];            // invariant: zero at kernel_launch entry
__device__ int g_off[T_NODES + 1];
__device__ int g_cur[T_NODES];
__device__ int g_csr_src[E_EDGES + 8];    // +8 pad (never written, stays 0)
// packed lookback word: low 2 bits = state, high 32 = value; zero at entry
__device__ volatile unsigned long long g_scan_word[SCAN_BLOCKS];

// ---------------- tf32 helpers ----------------
__device__ __forceinline__ uint32_t f2tf32(float v) {
    uint32_t r;
    asm("cvt.rna.tf32.f32 %0, %1;" : "=r"(r) : "f"(v));
    return r;
}
__device__ __forceinline__ void mma_tf32(float* d, const uint32_t* a, const uint32_t* b) {
    asm("mma.sync.aligned.m16n8k8.row.col.f32.tf32.tf32.f32 "
        "{%0,%1,%2,%3}, {%4,%5,%6,%7}, {%8,%9}, {%0,%1,%2,%3};"
        : "+f"(d[0]), "+f"(d[1]), "+f"(d[2]), "+f"(d[3])
        : "r"(a[0]), "r"(a[1]), "r"(a[2]), "r"(a[3]),
          "r"(b[0]), "r"(b[1]));
}

// ---------------- K1: tf32 GEMM, A direct-from-global (reg hi/lo), B smem-staged -
// CTA 128x128 tile, 8 warps (4m x 2n), warp tile 32x64. K in 2 chunks of 64.
__global__ void __launch_bounds__(256, 2)
gemm_kernel(const float* __restrict__ X,
            const float* __restrict__ Wl, const float* __restrict__ bl,
            const float* __restrict__ Wr, const float* __restrict__ br,
            const int* __restrict__ ei, int E) {
    // B_s: [k8(8)][na(16)][lane(32)][rg(2)] = 8192 u32 = 32KB per 64-k chunk
    __shared__ uint32_t B_s[8192];

    const int which = blockIdx.y;
    const float* __restrict__ W    = which ? Wr : Wl;
    const float* __restrict__ bvec = which ? br : bl;
    float* __restrict__ Y = which ? g_xr : g_xl;

    const int t = threadIdx.x;

    // histogram (fire-and-forget REDs, hidden under tensor work)
    {
        const int nthr = gridDim.x * gridDim.y * 256;
        int gid = (blockIdx.y * gridDim.x + blockIdx.x) * 256 + t;
        const int* __restrict__ dsts = ei + E;
        if ((E & 3) == 0) {
            const int4* __restrict__ d4 = (const int4*)dsts;
            for (int e = gid; e < (E >> 2); e += nthr) {
                int4 v = d4[e];
                atomicAdd(&g_deg[v.x], 1);
                atomicAdd(&g_deg[v.y], 1);
                atomicAdd(&g_deg[v.z], 1);
                atomicAdd(&g_deg[v.w], 1);
            }
        } else {
            for (int e = gid; e < E; e += nthr)
                atomicAdd(&g_deg[dsts[e]], 1);
        }
    }

    const int lane = t & 31;
    const int wid  = t >> 5;
    const int wm   = wid & 3;     // warp row group (32 rows)
    const int wn   = wid >> 2;    // warp col group (64 cols)
    const int rowBase = blockIdx.x * 128;

    const int tig  = lane & 3;    // thread-in-group (k within fragment)
    const int grp  = lane >> 2;   // group id (row/col within fragment)

    float d[2][8][4];
#pragma unroll
    for (int ma = 0; ma < 2; ma++)
#pragma unroll
        for (int na = 0; na < 8; na++)
#pragma unroll
            for (int r = 0; r < 4; r++) d[ma][na][r] = 0.f;

#pragma unroll 1
    for (int chunk = 0; chunk < 2; chunk++) {
        const int kcBase = chunk * 64;

        // ---- stage B chunk (64 k x 128 n) into fragment-ordered smem ----
        // 16 warp-steps; each step one (k8, na) atom: conflict-free STS.64.
#pragma unroll
        for (int q = 0; q < 16; q++) {
            int combo = q * 8 + wid;          // 0..127
            int k8 = combo & 7;
            int na = combo >> 3;              // 0..15
            int k0 = kcBase + k8 * 8 + tig;
            int n  = na * 8 + grp;
            uint2 val;
            val.x = f2tf32(W[k0 * HF_DIM + n]);
            val.y = f2tf32(W[(k0 + 4) * HF_DIM + n]);
            *(uint2*)&B_s[((k8 * 16 + na) * 32 + lane) * 2] = val;
        }
        __syncthreads();

        // ---- mainloop: A direct from global (hi/lo in regs), B from smem ----
#pragma unroll
        for (int k8 = 0; k8 < 8; k8++) {
            const int kk = kcBase + k8 * 8 + tig;
            uint32_t ah[2][4], al[2][4];
#pragma unroll
            for (int ma = 0; ma < 2; ma++) {
                int row = rowBase + wm * 32 + ma * 16 + grp;
                const float* xp = X + (size_t)row * C_DIM;
                float a0 = xp[kk];
                float a1 = xp[8 * C_DIM + kk];
                float a2 = xp[kk + 4];
                float a3 = xp[8 * C_DIM + kk + 4];
                ah[ma][0] = f2tf32(a0); al[ma][0] = f2tf32(a0 - __uint_as_float(ah[ma][0]));
                ah[ma][1] = f2tf32(a1); al[ma][1] = f2tf32(a1 - __uint_as_float(ah[ma][1]));
                ah[ma][2] = f2tf32(a2); al[ma][2] = f2tf32(a2 - __uint_as_float(ah[ma][2]));
                ah[ma][3] = f2tf32(a3); al[ma][3] = f2tf32(a3 - __uint_as_float(ah[ma][3]));
            }
            uint32_t bf[8][2];
#pragma unroll
            for (int na = 0; na < 8; na++) {
                uint2 b2 = *(const uint2*)&B_s[((k8 * 16 + wn * 8 + na) * 32 + lane) * 2];
                bf[na][0] = b2.x; bf[na][1] = b2.y;
            }
#pragma unroll
            for (int ma = 0; ma < 2; ma++)
#pragma unroll
                for (int na = 0; na < 8; na++) {
                    mma_tf32(d[ma][na], ah[ma], bf[na]);
                    mma_tf32(d[ma][na], al[ma], bf[na]);
                }
        }
        __syncthreads();
    }

    // ---- epilogue: add bias, store ----
#pragma unroll
    for (int ma = 0; ma < 2; ma++) {
        int row0 = rowBase + wm * 32 + ma * 16 + grp;
        int row1 = row0 + 8;
#pragma unroll
        for (int na = 0; na < 8; na++) {
            int col = wn * 64 + na * 8 + tig * 2;
            float2 bb = *(const float2*)&bvec[col];
            float2 o0 = { d[ma][na][0] + bb.x, d[ma][na][1] + bb.y };
            float2 o1 = { d[ma][na][2] + bb.x, d[ma][na][3] + bb.y };
            *(float2*)&Y[(size_t)row0 * HF_DIM + col] = o0;
            *(float2*)&Y[(size_t)row1 * HF_DIM + col] = o1;
        }
    }
}

// ---------------- K2: single-pass scan (warp-parallel lookback) ---------------
__global__ void __launch_bounds__(256)
scan_kernel() {
    const int b = blockIdx.x, t = threadIdx.x;
    const int lane = t & 31, w = t >> 5;
    int i = b * 256 + t;
    int v = (i < T_NODES) ? g_deg[i] : 0;
    if (i < T_NODES) g_deg[i] = 0;          // self-clean for next launch

    int x = v;
#pragma unroll
    for (int d = 1; d < 32; d <<= 1) {
        int y = __shfl_up_sync(0xffffffffu, x, d);
        if (lane >= d) x += y;
    }
    __shared__ int wt[8];
    if (lane == 31) wt[w] = x;
    __syncthreads();
    if (t < 8) {
        int y = wt[t];
#pragma unroll
        for (int d = 1; d < 8; d <<= 1) {
            int z = __shfl_up_sync(0x000000ffu, y, d);
            if (t >= d) y += z;
        }
        wt[t] = y;
    }
    __syncthreads();
    int incl  = x + (w ? wt[w - 1] : 0);
    int total = wt[7];

    __shared__ int s_excl;
    if (w == 0) {
        if (lane == 0)
            g_scan_word[b] = ((unsigned long long)(unsigned)total << 32) | 1ull;

        int excl = 0;
        int base = b - 1;
        while (base >= 0) {
            int idx = base - lane;
            unsigned long long wv = 0; int st = 0;
            if (idx >= 0) {
                do { wv = g_scan_word[idx]; st = (int)(wv & 3ull); } while (st == 0);
            }
            int val = (int)(wv >> 32);
            unsigned pm = __ballot_sync(0xffffffffu, idx >= 0 && st == 2);
            if (pm) {
                int fl = __ffs(pm) - 1;
                int contrib = (lane <= fl) ? val : 0;
#pragma unroll
                for (int d = 16; d > 0; d >>= 1)
                    contrib += __shfl_xor_sync(0xffffffffu, contrib, d);
                excl += contrib;
                break;
            } else {
                int contrib = (idx >= 0) ? val : 0;
#pragma unroll
                for (int d = 16; d > 0; d >>= 1)
                    contrib += __shfl_xor_sync(0xffffffffu, contrib, d);
                excl += contrib;
                base -= 32;
            }
        }
        if (lane == 0) {
            g_scan_word[b] = ((unsigned long long)(unsigned)(excl + total) << 32) | 2ull;
            s_excl = excl;
        }
    }
    __syncthreads();

    int off = s_excl + incl - v;
    if (i < T_NODES) {
        g_off[i] = off;
        g_cur[i] = off;
        if (i == T_NODES - 1) g_off[T_NODES] = off + v;
    }
}

// ---------------- K3: scatter (also re-zeroes scan words) ----------------
__global__ void __launch_bounds__(256)
scatter_kernel(const int* __restrict__ ei, int E) {
    int tid = blockIdx.x * 256 + threadIdx.x;
    if (tid < SCAN_BLOCKS) g_scan_word[tid] = 0ull;   // self-clean for next launch

    int base = tid * 4;
    if ((E & 3) == 0) {
        if (base < E) {
            int4 s = *(const int4*)(ei + base);
            int4 d = *(const int4*)(ei + E + base);
            int p0 = atomicAdd(&g_cur[d.x], 1);
            int p1 = atomicAdd(&g_cur[d.y], 1);
            int p2 = atomicAdd(&g_cur[d.z], 1);
            int p3 = atomicAdd(&g_cur[d.w], 1);
            g_csr_src[p0] = s.x;
            g_csr_src[p1] = s.y;
            g_csr_src[p2] = s.z;
            g_csr_src[p3] = s.w;
        }
    } else {
        for (int e = base; e < min(base + 4, E); e++) {
            int pos = atomicAdd(&g_cur[ei[E + e]], 1);
            g_csr_src[pos] = ei[e];
        }
    }
}

// ---------------- K4: softmax + aggregation (baseline-exp, unroll-2) ----------
__device__ __forceinline__ float edge_logit(float4 xs, float4 xr, float4 av) {
    float t0 = xs.x + xr.x, t1 = xs.y + xr.y, t2 = xs.z + xr.z, t3 = xs.w + xr.w;
    float l0 = fmaxf(t0, 0.f) + NEG_SLOPE * fminf(t0, 0.f);
    float l1 = fmaxf(t1, 0.f) + NEG_SLOPE * fminf(t1, 0.f);
    float l2 = fmaxf(t2, 0.f) + NEG_SLOPE * fminf(t2, 0.f);
    float l3 = fmaxf(t3, 0.f) + NEG_SLOPE * fminf(t3, 0.f);
    float p = l0 * av.x;
    p = fmaf(l1, av.y, p);
    p = fmaf(l2, av.z, p);
    p = fmaf(l3, av.w, p);
    p += __shfl_xor_sync(0xffffffffu, p, 1);
    p += __shfl_xor_sync(0xffffffffu, p, 2);
    p += __shfl_xor_sync(0xffffffffu, p, 4);
    p += __shfl_xor_sync(0xffffffffu, p, 8);
    return p;
}

__global__ void __launch_bounds__(256, 4)
agg_kernel(const float* __restrict__ att, const float* __restrict__ bias,
           float* __restrict__ out) {
    int warp_id = (blockIdx.x * blockDim.x + threadIdx.x) >> 5;
    int lane = threadIdx.x & 31;
    if (warp_id >= T_NODES) return;
    const int d = warp_id;
    const int fbase = lane * 4;

    // 32-bit byte-offset addressing into the gather tables
    const char* __restrict__ xlb = (const char*)g_xl;
    const unsigned loff = (unsigned)lane << 4;   // lane * 16 bytes

    float4 av  = *(const float4*)&att[fbase];
    float4 xr  = *(const float4*)((const char*)g_xr + ((unsigned)d << 9) + loff);
    float4 xld = *(const float4*)(xlb + ((unsigned)d << 9) + loff);

    const float lself = edge_logit(xld, xr, av);
    float den = 1.0f;
    float4 acc = xld;

    const int beg = g_off[d];
    const int n = g_off[d + 1] - beg;

    if (n > 0) {
        const int* __restrict__ sp = g_csr_src + beg;
        // unguarded prefetch: csr padded; over-reads hit valid/zero indices
        int s2 = __ldg(&sp[2]);
        int s3 = __ldg(&sp[3]);
        float4 x0 = *(const float4*)(xlb + ((unsigned)__ldg(&sp[0]) << 9) + loff);
        float4 x1 = *(const float4*)(xlb + ((unsigned)__ldg(&sp[1]) << 9) + loff);

        for (int i = 0; i < n; i += 2) {
            float4 x2 = *(const float4*)(xlb + ((unsigned)s2 << 9) + loff);
            float4 x3 = *(const float4*)(xlb + ((unsigned)s3 << 9) + loff);
            int s4 = __ldg(&sp[i + 4]);
            int s5 = __ldg(&sp[i + 5]);

            float l0 = edge_logit(x0, xr, av);
            float l1 = edge_logit(x1, xr, av);
            float w0 = __expf(l0 - lself);
            float w1 = (i + 1 < n) ? __expf(l1 - lself) : 0.f;

            den += w0 + w1;
            acc.x = fmaf(w0, x0.x, fmaf(w1, x1.x, acc.x));
            acc.y = fmaf(w0, x0.y, fmaf(w1, x1.y, acc.y));
            acc.z = fmaf(w0, x0.z, fmaf(w1, x1.z, acc.z));
            acc.w = fmaf(w0, x0.w, fmaf(w1, x1.w, acc.w));

            x0 = x2; x1 = x3;
            s2 = s4; s3 = s5;
        }
    }

    float inv = 1.0f / den;
    float4 bv = *(const float4*)&bias[fbase];
    float4 r;
    r.x = fmaf(acc.x, inv, bv.x);
    r.y = fmaf(acc.y, inv, bv.y);
    r.z = fmaf(acc.z, inv, bv.z);
    r.w = fmaf(acc.w, inv, bv.w);
    *(float4*)((char*)out + ((unsigned)d << 9) + loff) = r;
}

// ---------------- launch ----------------
extern "C" void kernel_launch(void* const* d_in, const int* in_sizes, int n_in,
                              void* d_out, int out_size) {
    const float* x    = (const float*)d_in[0];
    const int*   ei   = (const int*)d_in[1];
    const float* Wl   = (const float*)d_in[2];
    const float* bl   = (const float*)d_in[3];
    const float* Wr   = (const float*)d_in[4];
    const float* br   = (const float*)d_in[5];
    const float* att  = (const float*)d_in[6];
    const float* bias = (const float*)d_in[7];
    float* out = (float*)d_out;

    const int E = in_sizes[1] / 2;

    dim3 ggrid(T_NODES / 128, 2);
    gemm_kernel<<<ggrid, 256>>>(x, Wl, bl, Wr, br, ei, E);  // hist hidden inside

    scan_kernel<<<SCAN_BLOCKS, 256>>>();                    // zeroes g_deg
    scatter_kernel<<<(E / 4 + 255) / 256, 256>>>(ei, E);    // zeroes scan words
    agg_kernel<<<(T_NODES * 32 + 255) / 256, 256>>>(att, bias, out);
}

// round 8
// speedup vs baseline: 1.3563x; 1.0625x over previous
#include <cuda_runtime.h>
#include <cstdint>

#define T_NODES 80000          // B*N = 16*5000
#define C_DIM   128
#define HF_DIM  128            // H*F = 2*64
#define E_EDGES 1280000
#define SCAN_BLOCKS ((T_NODES + 255) / 256)   // 313
#define LOG2E 1.4426950408889634f

// ---------------- static device scratch (zero-initialized at load) ----------------
__device__ __align__(16) float g_xl[T_NODES * HF_DIM];   // 40.96 MB
__device__ __align__(16) float g_xr[T_NODES * HF_DIM];   // 40.96 MB
__device__ int g_deg[T_NODES];            // invariant: zero at kernel_launch entry
__device__ int g_off[T_NODES + 1];
__device__ int g_cur[T_NODES];
__device__ int g_csr_src[E_EDGES + 8];    // stores src byte offsets (src<<9); +8 pad = 0
// packed lookback word: low 2 bits = state, high 32 = value; zero at entry
__device__ volatile unsigned long long g_scan_word[SCAN_BLOCKS];

// ---------------- tf32 helpers ----------------
__device__ __forceinline__ uint32_t f2tf32(float v) {
    uint32_t r;
    asm("cvt.rna.tf32.f32 %0, %1;" : "=r"(r) : "f"(v));
    return r;
}
__device__ __forceinline__ void mma_tf32(float* d, const uint32_t* a, const uint32_t* b) {
    asm("mma.sync.aligned.m16n8k8.row.col.f32.tf32.tf32.f32 "
        "{%0,%1,%2,%3}, {%4,%5,%6,%7}, {%8,%9}, {%0,%1,%2,%3};"
        : "+f"(d[0]), "+f"(d[1]), "+f"(d[2]), "+f"(d[3])
        : "r"(a[0]), "r"(a[1]), "r"(a[2]), "r"(a[3]),
          "r"(b[0]), "r"(b[1]));
}

// ---------------- K1: tf32 GEMM (single-pass A from global regs, B smem) --------
// CTA 128x128 tile, 8 warps (4m x 2n), warp tile 32x64. K in 2 chunks of 64.
__global__ void __launch_bounds__(256, 2)
gemm_kernel(const float* __restrict__ X,
            const float* __restrict__ Wl, const float* __restrict__ bl,
            const float* __restrict__ Wr, const float* __restrict__ br,
            const int* __restrict__ ei, int E) {
    __shared__ uint32_t B_s[8192];   // [k8(8)][na(16)][lane(32)][rg(2)] = 32KB

    const int which = blockIdx.y;
    const float* __restrict__ W    = which ? Wr : Wl;
    const float* __restrict__ bvec = which ? br : bl;
    float* __restrict__ Y = which ? g_xr : g_xl;

    const int t = threadIdx.x;

    // histogram (fire-and-forget REDs, hidden under tensor work)
    {
        const int nthr = gridDim.x * gridDim.y * 256;
        int gid = (blockIdx.y * gridDim.x + blockIdx.x) * 256 + t;
        const int* __restrict__ dsts = ei + E;
        if ((E & 3) == 0) {
            const int4* __restrict__ d4 = (const int4*)dsts;
            for (int e = gid; e < (E >> 2); e += nthr) {
                int4 v = d4[e];
                atomicAdd(&g_deg[v.x], 1);
                atomicAdd(&g_deg[v.y], 1);
                atomicAdd(&g_deg[v.z], 1);
                atomicAdd(&g_deg[v.w], 1);
            }
        } else {
            for (int e = gid; e < E; e += nthr)
                atomicAdd(&g_deg[dsts[e]], 1);
        }
    }

    const int lane = t & 31;
    const int wid  = t >> 5;
    const int wm   = wid & 3;
    const int wn   = wid >> 2;
    const int rowBase = blockIdx.x * 128;

    const int tig  = lane & 3;
    const int grp  = lane >> 2;

    float d[2][8][4];
#pragma unroll
    for (int ma = 0; ma < 2; ma++)
#pragma unroll
        for (int na = 0; na < 8; na++)
#pragma unroll
            for (int r = 0; r < 4; r++) d[ma][na][r] = 0.f;

#pragma unroll 1
    for (int chunk = 0; chunk < 2; chunk++) {
        const int kcBase = chunk * 64;

        // stage B chunk (64 k x 128 n) fragment-ordered, conflict-free STS.64
#pragma unroll
        for (int q = 0; q < 16; q++) {
            int combo = q * 8 + wid;
            int k8 = combo & 7;
            int na = combo >> 3;
            int k0 = kcBase + k8 * 8 + tig;
            int n  = na * 8 + grp;
            uint2 val;
            val.x = f2tf32(W[k0 * HF_DIM + n]);
            val.y = f2tf32(W[(k0 + 4) * HF_DIM + n]);
            *(uint2*)&B_s[((k8 * 16 + na) * 32 + lane) * 2] = val;
        }
        __syncthreads();

#pragma unroll
        for (int k8 = 0; k8 < 8; k8++) {
            const int kk = kcBase + k8 * 8 + tig;
            uint32_t af[2][4];
#pragma unroll
            for (int ma = 0; ma < 2; ma++) {
                int row = rowBase + wm * 32 + ma * 16 + grp;
                const float* xp = X + (size_t)row * C_DIM;
                af[ma][0] = f2tf32(xp[kk]);
                af[ma][1] = f2tf32(xp[8 * C_DIM + kk]);
                af[ma][2] = f2tf32(xp[kk + 4]);
                af[ma][3] = f2tf32(xp[8 * C_DIM + kk + 4]);
            }
            uint32_t bf[8][2];
#pragma unroll
            for (int na = 0; na < 8; na++) {
                uint2 b2 = *(const uint2*)&B_s[((k8 * 16 + wn * 8 + na) * 32 + lane) * 2];
                bf[na][0] = b2.x; bf[na][1] = b2.y;
            }
#pragma unroll
            for (int ma = 0; ma < 2; ma++)
#pragma unroll
                for (int na = 0; na < 8; na++)
                    mma_tf32(d[ma][na], af[ma], bf[na]);
        }
        __syncthreads();
    }

    // epilogue: add bias, store
#pragma unroll
    for (int ma = 0; ma < 2; ma++) {
        int row0 = rowBase + wm * 32 + ma * 16 + grp;
        int row1 = row0 + 8;
#pragma unroll
        for (int na = 0; na < 8; na++) {
            int col = wn * 64 + na * 8 + tig * 2;
            float2 bb = *(const float2*)&bvec[col];
            float2 o0 = { d[ma][na][0] + bb.x, d[ma][na][1] + bb.y };
            float2 o1 = { d[ma][na][2] + bb.x, d[ma][na][3] + bb.y };
            *(float2*)&Y[(size_t)row0 * HF_DIM + col] = o0;
            *(float2*)&Y[(size_t)row1 * HF_DIM + col] = o1;
        }
    }
}

// ---------------- K2: single-pass scan (warp-parallel lookback) ---------------
__global__ void __launch_bounds__(256)
scan_kernel() {
    const int b = blockIdx.x, t = threadIdx.x;
    const int lane = t & 31, w = t >> 5;
    int i = b * 256 + t;
    int v = (i < T_NODES) ? g_deg[i] : 0;
    if (i < T_NODES) g_deg[i] = 0;          // self-clean for next launch

    int x = v;
#pragma unroll
    for (int d = 1; d < 32; d <<= 1) {
        int y = __shfl_up_sync(0xffffffffu, x, d);
        if (lane >= d) x += y;
    }
    __shared__ int wt[8];
    if (lane == 31) wt[w] = x;
    __syncthreads();
    if (t < 8) {
        int y = wt[t];
#pragma unroll
        for (int d = 1; d < 8; d <<= 1) {
            int z = __shfl_up_sync(0x000000ffu, y, d);
            if (t >= d) y += z;
        }
        wt[t] = y;
    }
    __syncthreads();
    int incl  = x + (w ? wt[w - 1] : 0);
    int total = wt[7];

    __shared__ int s_excl;
    if (w == 0) {
        if (lane == 0)
            g_scan_word[b] = ((unsigned long long)(unsigned)total << 32) | 1ull;

        int excl = 0;
        int base = b - 1;
        while (base >= 0) {
            int idx = base - lane;
            unsigned long long wv = 0; int st = 0;
            if (idx >= 0) {
                do { wv = g_scan_word[idx]; st = (int)(wv & 3ull); } while (st == 0);
            }
            int val = (int)(wv >> 32);
            unsigned pm = __ballot_sync(0xffffffffu, idx >= 0 && st == 2);
            if (pm) {
                int fl = __ffs(pm) - 1;
                int contrib = (lane <= fl) ? val : 0;
#pragma unroll
                for (int d = 16; d > 0; d >>= 1)
                    contrib += __shfl_xor_sync(0xffffffffu, contrib, d);
                excl += contrib;
                break;
            } else {
                int contrib = (idx >= 0) ? val : 0;
#pragma unroll
                for (int d = 16; d > 0; d >>= 1)
                    contrib += __shfl_xor_sync(0xffffffffu, contrib, d);
                excl += contrib;
                base -= 32;
            }
        }
        if (lane == 0) {
            g_scan_word[b] = ((unsigned long long)(unsigned)(excl + total) << 32) | 2ull;
            s_excl = excl;
        }
    }
    __syncthreads();

    int off = s_excl + incl - v;
    if (i < T_NODES) {
        g_off[i] = off;
        g_cur[i] = off;
        if (i == T_NODES - 1) g_off[T_NODES] = off + v;
    }
}

// ---------------- K3: scatter (stores src byte offsets; re-zeroes scan words) --
__global__ void __launch_bounds__(256)
scatter_kernel(const int* __restrict__ ei, int E) {
    int tid = blockIdx.x * 256 + threadIdx.x;
    if (tid < SCAN_BLOCKS) g_scan_word[tid] = 0ull;   // self-clean for next launch

    int base = tid * 4;
    if ((E & 3) == 0) {
        if (base < E) {
            int4 s = *(const int4*)(ei + base);
            int4 d = *(const int4*)(ei + E + base);
            int p0 = atomicAdd(&g_cur[d.x], 1);
            int p1 = atomicAdd(&g_cur[d.y], 1);
            int p2 = atomicAdd(&g_cur[d.z], 1);
            int p3 = atomicAdd(&g_cur[d.w], 1);
            g_csr_src[p0] = s.x << 9;      // pre-scaled byte offset (row * 512B)
            g_csr_src[p1] = s.y << 9;
            g_csr_src[p2] = s.z << 9;
            g_csr_src[p3] = s.w << 9;
        }
    } else {
        for (int e = base; e < min(base + 4, E); e++) {
            int pos = atomicAdd(&g_cur[ei[E + e]], 1);
            g_csr_src[pos] = ei[e] << 9;
        }
    }
}

// ---------------- K4: softmax + aggregation (log2-domain, abs-folded leaky) ----
// leaky(t) = 0.6t + 0.4|t|; logit pre-scaled by log2e -> w = exp2(l - lself).
__device__ __forceinline__ float edge_logit(float4 xs, float4 xr,
                                            float4 av6, float4 av4) {
    float t0 = xs.x + xr.x, t1 = xs.y + xr.y, t2 = xs.z + xr.z, t3 = xs.w + xr.w;
    float p;
    p = t0 * av6.x;
    p = fmaf(fabsf(t0), av4.x, p);
    p = fmaf(t1, av6.y, p);
    p = fmaf(fabsf(t1), av4.y, p);
    p = fmaf(t2, av6.z, p);
    p = fmaf(fabsf(t2), av4.z, p);
    p = fmaf(t3, av6.w, p);
    p = fmaf(fabsf(t3), av4.w, p);
    p += __shfl_xor_sync(0xffffffffu, p, 1);
    p += __shfl_xor_sync(0xffffffffu, p, 2);
    p += __shfl_xor_sync(0xffffffffu, p, 4);
    p += __shfl_xor_sync(0xffffffffu, p, 8);
    return p;
}

__global__ void __launch_bounds__(256, 4)
agg_kernel(const float* __restrict__ att, const float* __restrict__ bias,
           float* __restrict__ out) {
    int warp_id = (blockIdx.x * blockDim.x + threadIdx.x) >> 5;
    int lane = threadIdx.x & 31;
    if (warp_id >= T_NODES) return;
    const int d = warp_id;
    const int fbase = lane * 4;

    const char* __restrict__ xlb = (const char*)g_xl;
    const unsigned loff = (unsigned)lane << 4;   // lane * 16 bytes

    float4 a = *(const float4*)&att[fbase];
    float4 av6, av4;
    av6.x = a.x * (0.6f * LOG2E); av4.x = a.x * (0.4f * LOG2E);
    av6.y = a.y * (0.6f * LOG2E); av4.y = a.y * (0.4f * LOG2E);
    av6.z = a.z * (0.6f * LOG2E); av4.z = a.z * (0.4f * LOG2E);
    av6.w = a.w * (0.6f * LOG2E); av4.w = a.w * (0.4f * LOG2E);

    float4 xr  = *(const float4*)((const char*)g_xr + ((unsigned)d << 9) + loff);
    float4 xld = *(const float4*)(xlb + ((unsigned)d << 9) + loff);

    const float lself = edge_logit(xld, xr, av6, av4);   // log2-domain baseline
    float den = 1.0f;
    float4 acc = xld;

    const int beg = g_off[d];
    const int n = g_off[d + 1] - beg;

    if (n > 0) {
        const int* __restrict__ sp = g_csr_src + beg;   // entries are byte offsets
        int s2 = __ldg(&sp[2]);
        int s3 = __ldg(&sp[3]);
        float4 x0 = *(const float4*)(xlb + (unsigned)__ldg(&sp[0]) + loff);
        float4 x1 = *(const float4*)(xlb + (unsigned)__ldg(&sp[1]) + loff);

        for (int i = 0; i < n; i += 2) {
            float4 x2 = *(const float4*)(xlb + (unsigned)s2 + loff);
            float4 x3 = *(const float4*)(xlb + (unsigned)s3 + loff);
            int s4 = __ldg(&sp[i + 4]);
            int s5 = __ldg(&sp[i + 5]);

            float l0 = edge_logit(x0, xr, av6, av4);
            float l1 = edge_logit(x1, xr, av6, av4);
            float w0 = exp2f(l0 - lself);
            float w1 = (i + 1 < n) ? exp2f(l1 - lself) : 0.f;

            den += w0 + w1;
            acc.x = fmaf(w0, x0.x, fmaf(w1, x1.x, acc.x));
            acc.y = fmaf(w0, x0.y, fmaf(w1, x1.y, acc.y));
            acc.z = fmaf(w0, x0.z, fmaf(w1, x1.z, acc.z));
            acc.w = fmaf(w0, x0.w, fmaf(w1, x1.w, acc.w));

            x0 = x2; x1 = x3;
            s2 = s4; s3 = s5;
        }
    }

    float inv = 1.0f / den;
    float4 bv = *(const float4*)&bias[fbase];
    float4 r;
    r.x = fmaf(acc.x, inv, bv.x);
    r.y = fmaf(acc.y, inv, bv.y);
    r.z = fmaf(acc.z, inv, bv.z);
    r.w = fmaf(acc.w, inv, bv.w);
    *(float4*)((char*)out + ((unsigned)d << 9) + loff) = r;
}

// ---------------- launch ----------------
extern "C" void kernel_launch(void* const* d_in, const int* in_sizes, int n_in,
                              void* d_out, int out_size) {
    const float* x    = (const float*)d_in[0];
    const int*   ei   = (const int*)d_in[1];
    const float* Wl   = (const float*)d_in[2];
    const float* bl   = (const float*)d_in[3];
    const float* Wr   = (const float*)d_in[4];
    const float* br   = (const float*)d_in[5];
    const float* att  = (const float*)d_in[6];
    const float* bias = (const float*)d_in[7];
    float* out = (float*)d_out;

    const int E = in_sizes[1] / 2;

    dim3 ggrid(T_NODES / 128, 2);
    gemm_kernel<<<ggrid, 256>>>(x, Wl, bl, Wr, br, ei, E);  // hist hidden inside

    scan_kernel<<<SCAN_BLOCKS, 256>>>();                    // zeroes g_deg
    scatter_kernel<<<(E / 4 + 255) / 256, 256>>>(ei, E);    // zeroes scan words
    agg_kernel<<<(T_NODES * 32 + 255) / 256, 256>>>(att, bias, out);
}

// round 10
// speedup vs baseline: 1.3951x; 1.0286x over previous
#include <cuda_runtime.h>
#include <cstdint>

#define T_NODES 80000          // B*N = 16*5000
#define C_DIM   128
#define HF_DIM  128            // H*F = 2*64
#define E_EDGES 1280000
#define SCAN_BLOCKS ((T_NODES + 255) / 256)   // 313
#define LOG2E 1.4426950408889634f

// ---------------- static device scratch (zero-initialized at load) ----------------
__device__ __align__(16) float g_xl[T_NODES * HF_DIM];   // 40.96 MB
__device__ __align__(16) float g_xr[T_NODES * HF_DIM];   // 40.96 MB
__device__ int g_deg[T_NODES];            // invariant: zero at kernel_launch entry
__device__ int g_off[T_NODES + 1];
__device__ int g_cur[T_NODES];
__device__ int g_csr_src[E_EDGES + 8];    // stores src byte offsets (src<<9); +8 pad = 0
// packed lookback word: low 2 bits = state, high 32 = value; zero at entry
__device__ volatile unsigned long long g_scan_word[SCAN_BLOCKS];

// ---------------- tf32 helpers ----------------
__device__ __forceinline__ uint32_t f2tf32(float v) {
    uint32_t r;
    asm("cvt.rna.tf32.f32 %0, %1;" : "=r"(r) : "f"(v));
    return r;
}
__device__ __forceinline__ void mma_tf32(float* d, const uint32_t* a, const uint32_t* b) {
    asm("mma.sync.aligned.m16n8k8.row.col.f32.tf32.tf32.f32 "
        "{%0,%1,%2,%3}, {%4,%5,%6,%7}, {%8,%9}, {%0,%1,%2,%3};"
        : "+f"(d[0]), "+f"(d[1]), "+f"(d[2]), "+f"(d[3])
        : "r"(a[0]), "r"(a[1]), "r"(a[2]), "r"(a[3]),
          "r"(b[0]), "r"(b[1]));
}

// ---------------- K1: fused tf32 GEMM pair (xl AND xr in one CTA) --------------
// 512 threads / 16 warps. Warp-group g=wid>>3 computes Y_g = X @ W_g (+b_g):
// 8 warps per group, warp tile 32x64 of the 128x128 row-tile.
// K processed in 4 chunks of 32. A (X chunk) staged ONCE in fragment-ordered
// smem (XOR-k8 bank skew), shared by both groups. Smem = 16KB A + 2x16KB B = 48KB.
__global__ void __launch_bounds__(512, 1)
gemm_kernel(const float* __restrict__ X,
            const float* __restrict__ Wl, const float* __restrict__ bl,
            const float* __restrict__ Wr, const float* __restrict__ br,
            const int* __restrict__ ei, int E) {
    __shared__ uint32_t A_s[4096];       // [k8(4)][ma(8)][lane(32)][rg(4)] XOR-skewed
    __shared__ uint32_t B_s[2][4096];    // per group: [k8(4)][na(16)][lane(32)][rg(2)]

    const int t = threadIdx.x;

    // histogram (fire-and-forget REDs, hidden under tensor work)
    {
        const int nthr = gridDim.x * 512;
        int gid = blockIdx.x * 512 + t;
        const int* __restrict__ dsts = ei + E;
        if ((E & 3) == 0) {
            const int4* __restrict__ d4 = (const int4*)dsts;
            for (int e = gid; e < (E >> 2); e += nthr) {
                int4 v = d4[e];
                atomicAdd(&g_deg[v.x], 1);
                atomicAdd(&g_deg[v.y], 1);
                atomicAdd(&g_deg[v.z], 1);
                atomicAdd(&g_deg[v.w], 1);
            }
        } else {
            for (int e = gid; e < E; e += nthr)
                atomicAdd(&g_deg[dsts[e]], 1);
        }
    }

    const int lane = t & 31;
    const int wid  = t >> 5;          // 0..15
    const int g    = wid >> 3;        // warp group: 0 = xl, 1 = xr
    const int w8   = wid & 7;
    const int wm   = w8 & 3;          // row group (32 rows)
    const int wn   = w8 >> 2;         // col group (64 cols)
    const int rowBase = blockIdx.x * 128;

    const int tig = lane & 3;
    const int grp = lane >> 2;

    const float* __restrict__ Wg    = g ? Wr : Wl;
    const float* __restrict__ bvec  = g ? br : bl;
    float* __restrict__ Y           = g ? g_xr : g_xl;

    // A staging constants for this thread: row/k8 fixed across chunks
    const int a_row = t >> 2;          // 0..127
    const int a_k8  = t & 3;           // chunk-local k8
    const int a_r   = a_row & 15;
    const int a_ma  = a_row >> 4;
    const int a_atombase = (a_k8 * 8 + a_ma) * 128;
    const int a_skew = a_k8 * 4;

    float d[2][8][4];
#pragma unroll
    for (int ma = 0; ma < 2; ma++)
#pragma unroll
        for (int na = 0; na < 8; na++)
#pragma unroll
            for (int r = 0; r < 4; r++) d[ma][na][r] = 0.f;

#pragma unroll 1
    for (int chunk = 0; chunk < 4; chunk++) {
        const int kc = chunk * 32;

        // ---- stage A chunk (128 rows x 32 k): coalesced LDG.128, skewed STS ----
        {
            const float* xp = X + (size_t)(rowBase + a_row) * C_DIM + kc + a_k8 * 8;
            float4 v0 = *(const float4*)xp;
            float4 v1 = *(const float4*)(xp + 4);
            float vv[8] = { v0.x, v0.y, v0.z, v0.w, v1.x, v1.y, v1.z, v1.w };
#pragma unroll
            for (int j = 0; j < 8; j++) {
                int ln = (a_r & 7) * 4 + (j & 3);
                int rg = (a_r >> 3) + 2 * (j >> 2);
                A_s[a_atombase + ((ln * 4 + rg) ^ a_skew)] = f2tf32(vv[j]);
            }
        }
        // ---- stage both B chunks (32 k x 128 n each), fragment-ordered ----
#pragma unroll
        for (int q = 0; q < 8; q++) {
            int combo = q * 16 + wid;          // 0..127
            int bg  = combo >> 6;              // which W
            int rem = combo & 63;
            int na  = rem >> 2;
            int k8  = rem & 3;
            const float* __restrict__ WW = bg ? Wr : Wl;
            int k0 = kc + k8 * 8 + tig;
            int n  = na * 8 + grp;
            uint2 val;
            val.x = f2tf32(WW[k0 * HF_DIM + n]);
            val.y = f2tf32(WW[(k0 + 4) * HF_DIM + n]);
            *(uint2*)&B_s[bg][((k8 * 16 + na) * 32 + lane) * 2] = val;
        }
        __syncthreads();

        // ---- mainloop: each warp-group computes its own output tile ----
#pragma unroll
        for (int k8 = 0; k8 < 4; k8++) {
            const int skew = k8 * 4;
            uint32_t af[2][4];
#pragma unroll
            for (int ma = 0; ma < 2; ma++) {
                int base = (k8 * 8 + wm * 2 + ma) * 128 + ((lane * 4) ^ skew);
                uint4 h = *(const uint4*)&A_s[base];
                af[ma][0] = h.x; af[ma][1] = h.y; af[ma][2] = h.z; af[ma][3] = h.w;
            }
            uint32_t bf[8][2];
#pragma unroll
            for (int na = 0; na < 8; na++) {
                uint2 b2 = *(const uint2*)&B_s[g][((k8 * 16 + wn * 8 + na) * 32 + lane) * 2];
                bf[na][0] = b2.x; bf[na][1] = b2.y;
            }
#pragma unroll
            for (int ma = 0; ma < 2; ma++)
#pragma unroll
                for (int na = 0; na < 8; na++)
                    mma_tf32(d[ma][na], af[ma], bf[na]);
        }
        __syncthreads();
    }

    // ---- epilogue: add bias, store ----
#pragma unroll
    for (int ma = 0; ma < 2; ma++) {
        int row0 = rowBase + wm * 32 + ma * 16 + grp;
        int row1 = row0 + 8;
#pragma unroll
        for (int na = 0; na < 8; na++) {
            int col = wn * 64 + na * 8 + tig * 2;
            float2 bb = *(const float2*)&bvec[col];
            float2 o0 = { d[ma][na][0] + bb.x, d[ma][na][1] + bb.y };
            float2 o1 = { d[ma][na][2] + bb.x, d[ma][na][3] + bb.y };
            *(float2*)&Y[(size_t)row0 * HF_DIM + col] = o0;
            *(float2*)&Y[(size_t)row1 * HF_DIM + col] = o1;
        }
    }
}

// ---------------- K2: single-pass scan (warp-parallel lookback) ---------------
__global__ void __launch_bounds__(256)
scan_kernel() {
    const int b = blockIdx.x, t = threadIdx.x;
    const int lane = t & 31, w = t >> 5;
    int i = b * 256 + t;
    int v = (i < T_NODES) ? g_deg[i] : 0;
    if (i < T_NODES) g_deg[i] = 0;          // self-clean for next launch

    int x = v;
#pragma unroll
    for (int d = 1; d < 32; d <<= 1) {
        int y = __shfl_up_sync(0xffffffffu, x, d);
        if (lane >= d) x += y;
    }
    __shared__ int wt[8];
    if (lane == 31) wt[w] = x;
    __syncthreads();
    if (t < 8) {
        int y = wt[t];
#pragma unroll
        for (int d = 1; d < 8; d <<= 1) {
            int z = __shfl_up_sync(0x000000ffu, y, d);
            if (t >= d) y += z;
        }
        wt[t] = y;
    }
    __syncthreads();
    int incl  = x + (w ? wt[w - 1] : 0);
    int total = wt[7];

    __shared__ int s_excl;
    if (w == 0) {
        if (lane == 0)
            g_scan_word[b] = ((unsigned long long)(unsigned)total << 32) | 1ull;

        int excl = 0;
        int base = b - 1;
        while (base >= 0) {
            int idx = base - lane;
            unsigned long long wv = 0; int st = 0;
            if (idx >= 0) {
                do { wv = g_scan_word[idx]; st = (int)(wv & 3ull); } while (st == 0);
            }
            int val = (int)(wv >> 32);
            unsigned pm = __ballot_sync(0xffffffffu, idx >= 0 && st == 2);
            if (pm) {
                int fl = __ffs(pm) - 1;
                int contrib = (lane <= fl) ? val : 0;
#pragma unroll
                for (int d = 16; d > 0; d >>= 1)
                    contrib += __shfl_xor_sync(0xffffffffu, contrib, d);
                excl += contrib;
                break;
            } else {
                int contrib = (idx >= 0) ? val : 0;
#pragma unroll
                for (int d = 16; d > 0; d >>= 1)
                    contrib += __shfl_xor_sync(0xffffffffu, contrib, d);
                excl += contrib;
                base -= 32;
            }
        }
        if (lane == 0) {
            g_scan_word[b] = ((unsigned long long)(unsigned)(excl + total) << 32) | 2ull;
            s_excl = excl;
        }
    }
    __syncthreads();

    int off = s_excl + incl - v;
    if (i < T_NODES) {
        g_off[i] = off;
        g_cur[i] = off;
        if (i == T_NODES - 1) g_off[T_NODES] = off + v;
    }
}

// ---------------- K3: scatter (stores src byte offsets; re-zeroes scan words) --
__global__ void __launch_bounds__(256)
scatter_kernel(const int* __restrict__ ei, int E) {
    int tid = blockIdx.x * 256 + threadIdx.x;
    if (tid < SCAN_BLOCKS) g_scan_word[tid] = 0ull;   // self-clean for next launch

    int base = tid * 4;
    if ((E & 3) == 0) {
        if (base < E) {
            int4 s = *(const int4*)(ei + base);
            int4 d = *(const int4*)(ei + E + base);
            int p0 = atomicAdd(&g_cur[d.x], 1);
            int p1 = atomicAdd(&g_cur[d.y], 1);
            int p2 = atomicAdd(&g_cur[d.z], 1);
            int p3 = atomicAdd(&g_cur[d.w], 1);
            g_csr_src[p0] = s.x << 9;      // pre-scaled byte offset (row * 512B)
            g_csr_src[p1] = s.y << 9;
            g_csr_src[p2] = s.z << 9;
            g_csr_src[p3] = s.w << 9;
        }
    } else {
        for (int e = base; e < min(base + 4, E); e++) {
            int pos = atomicAdd(&g_cur[ei[E + e]], 1);
            g_csr_src[pos] = ei[e] << 9;
        }
    }
}

// ---------------- K4: softmax + aggregation (log2-domain, abs-folded leaky) ----
// leaky(t) = 0.6t + 0.4|t|; logit pre-scaled by log2e -> w = exp2(l - lself).
__device__ __forceinline__ float edge_logit(float4 xs, float4 xr,
                                            float4 av6, float4 av4) {
    float t0 = xs.x + xr.x, t1 = xs.y + xr.y, t2 = xs.z + xr.z, t3 = xs.w + xr.w;
    float p;
    p = t0 * av6.x;
    p = fmaf(fabsf(t0), av4.x, p);
    p = fmaf(t1, av6.y, p);
    p = fmaf(fabsf(t1), av4.y, p);
    p = fmaf(t2, av6.z, p);
    p = fmaf(fabsf(t2), av4.z, p);
    p = fmaf(t3, av6.w, p);
    p = fmaf(fabsf(t3), av4.w, p);
    p += __shfl_xor_sync(0xffffffffu, p, 1);
    p += __shfl_xor_sync(0xffffffffu, p, 2);
    p += __shfl_xor_sync(0xffffffffu, p, 4);
    p += __shfl_xor_sync(0xffffffffu, p, 8);
    return p;
}

__global__ void __launch_bounds__(256, 4)
agg_kernel(const float* __restrict__ att, const float* __restrict__ bias,
           float* __restrict__ out) {
    int warp_id = (blockIdx.x * blockDim.x + threadIdx.x) >> 5;
    int lane = threadIdx.x & 31;
    if (warp_id >= T_NODES) return;
    const int d = warp_id;
    const int fbase = lane * 4;

    const char* __restrict__ xlb = (const char*)g_xl;
    const unsigned loff = (unsigned)lane << 4;   // lane * 16 bytes

    float4 a = *(const float4*)&att[fbase];
    float4 av6, av4;
    av6.x = a.x * (0.6f * LOG2E); av4.x = a.x * (0.4f * LOG2E);
    av6.y = a.y * (0.6f * LOG2E); av4.y = a.y * (0.4f * LOG2E);
    av6.z = a.z * (0.6f * LOG2E); av4.z = a.z * (0.4f * LOG2E);
    av6.w = a.w * (0.6f * LOG2E); av4.w = a.w * (0.4f * LOG2E);

    float4 xr  = *(const float4*)((const char*)g_xr + ((unsigned)d << 9) + loff);
    float4 xld = *(const float4*)(xlb + ((unsigned)d << 9) + loff);

    const float lself = edge_logit(xld, xr, av6, av4);   // log2-domain baseline
    float den = 1.0f;
    float4 acc = xld;

    const int beg = g_off[d];
    const int n = g_off[d + 1] - beg;

    if (n > 0) {
        const int* __restrict__ sp = g_csr_src + beg;   // entries are byte offsets
        int s2 = __ldg(&sp[2]);
        int s3 = __ldg(&sp[3]);
        float4 x0 = *(const float4*)(xlb + (unsigned)__ldg(&sp[0]) + loff);
        float4 x1 = *(const float4*)(xlb + (unsigned)__ldg(&sp[1]) + loff);

        const int n2 = n & ~1;
        for (int i = 0; i < n2; i += 2) {
            float4 x2 = *(const float4*)(xlb + (unsigned)s2 + loff);
            float4 x3 = *(const float4*)(xlb + (unsigned)s3 + loff);
            int s4 = __ldg(&sp[i + 4]);
            int s5 = __ldg(&sp[i + 5]);

            float l0 = edge_logit(x0, xr, av6, av4);
            float l1 = edge_logit(x1, xr, av6, av4);
            float w0 = exp2f(l0 - lself);
            float w1 = exp2f(l1 - lself);

            den += w0 + w1;
            acc.x = fmaf(w0, x0.x, fmaf(w1, x1.x, acc.x));
            acc.y = fmaf(w0, x0.y, fmaf(w1, x1.y, acc.y));
            acc.z = fmaf(w0, x0.z, fmaf(w1, x1.z, acc.z));
            acc.w = fmaf(w0, x0.w, fmaf(w1, x1.w, acc.w));

            x0 = x2; x1 = x3;
            s2 = s4; s3 = s5;
        }
        if (n & 1) {
            // after the loop, x0 holds edge n-1
            float l0 = edge_logit(x0, xr, av6, av4);
            float w0 = exp2f(l0 - lself);
            den += w0;
            acc.x = fmaf(w0, x0.x, acc.x);
            acc.y = fmaf(w0, x0.y, acc.y);
            acc.z = fmaf(w0, x0.z, acc.z);
            acc.w = fmaf(w0, x0.w, acc.w);
        }
    }

    float inv = 1.0f / den;
    float4 bv = *(const float4*)&bias[fbase];
    float4 r;
    r.x = fmaf(acc.x, inv, bv.x);
    r.y = fmaf(acc.y, inv, bv.y);
    r.z = fmaf(acc.z, inv, bv.z);
    r.w = fmaf(acc.w, inv, bv.w);
    *(float4*)((char*)out + ((unsigned)d << 9) + loff) = r;
}

// ---------------- launch ----------------
extern "C" void kernel_launch(void* const* d_in, const int* in_sizes, int n_in,
                              void* d_out, int out_size) {
    const float* x    = (const float*)d_in[0];
    const int*   ei   = (const int*)d_in[1];
    const float* Wl   = (const float*)d_in[2];
    const float* bl   = (const float*)d_in[3];
    const float* Wr   = (const float*)d_in[4];
    const float* br   = (const float*)d_in[5];
    const float* att  = (const float*)d_in[6];
    const float* bias = (const float*)d_in[7];
    float* out = (float*)d_out;

    const int E = in_sizes[1] / 2;

    gemm_kernel<<<T_NODES / 128, 512>>>(x, Wl, bl, Wr, br, ei, E);  // both GEMMs + hist

    scan_kernel<<<SCAN_BLOCKS, 256>>>();                    // zeroes g_deg
    scatter_kernel<<<(E / 4 + 255) / 256, 256>>>(ei, E);    // zeroes scan words
    agg_kernel<<<(T_NODES * 32 + 255) / 256, 256>>>(att, bias, out);
}